// round 1
// baseline (speedup 1.0000x reference)
#include <cuda_runtime.h>

// LeakyCascade: s[t] = a*s[t-1] + (1-a)*x[t],  a = exp(-dt/tau_m)
// B=8, T=4096, D=256, M=8.  Blocked-scan decomposition over T.

#define BB 8
#define TT 4096
#define DD 256
#define MM 8
#define CC 32            // chunks along T
#define LL (TT / CC)     // 128 steps per chunk
#define D4 (DD / 4)      // 64 float4 lanes per (b,m) row

// Scratch (static device globals — no allocation in kernel_launch)
__device__ float g_send[BB * MM * CC * DD];  // local chunk end-states (2 MB)
__device__ float g_sin [BB * MM * CC * DD];  // true chunk start-states (2 MB)
__device__ float g_A   [BB * MM * CC];       // per-chunk total decay

// ---------------------------------------------------------------------------
// Phase 1: per-chunk local scan from s=0 ; emit s_end and chunk decay A.
// grid = (C, M, B), block = 64 threads (each owns 4 consecutive d via float4)
// ---------------------------------------------------------------------------
__global__ void __launch_bounds__(64) lc_phase1(
    const float* __restrict__ x, const float* __restrict__ delta,
    const float* __restrict__ tau)
{
    const int c = blockIdx.x, m = blockIdx.y, b = blockIdx.z;
    const int tid = threadIdx.x;

    __shared__ float s_alpha[LL];
    __shared__ float s_red[2];

    const float inv_tau = 1.0f / tau[m];
    const int t0 = c * LL;
    const float* drow = delta + b * TT;

    // Stage alpha for this chunk; accumulate sum of clamped dt for chunk decay.
    float dsum = 0.0f;
    #pragma unroll
    for (int i = tid; i < LL; i += 64) {
        const int t = t0 + i;
        float dt = (t == 0) ? 0.0f : fmaxf(drow[t] - drow[t - 1], 0.0f);
        dsum += dt;
        s_alpha[i] = expf(-dt * inv_tau);
    }
    #pragma unroll
    for (int off = 16; off > 0; off >>= 1)
        dsum += __shfl_down_sync(0xffffffffu, dsum, off);
    if ((tid & 31) == 0) s_red[tid >> 5] = dsum;
    __syncthreads();

    // Local scan from zero state.
    float4 s = make_float4(0.f, 0.f, 0.f, 0.f);
    const float4* xp = (const float4*)x + (b * TT + t0) * D4 + tid;
    #pragma unroll 4
    for (int i = 0; i < LL; i++) {
        const float a  = s_alpha[i];
        const float om = 1.0f - a;
        const float4 xv = xp[i * D4];
        s.x = fmaf(a, s.x, om * xv.x);
        s.y = fmaf(a, s.y, om * xv.y);
        s.z = fmaf(a, s.z, om * xv.z);
        s.w = fmaf(a, s.w, om * xv.w);
    }

    const int bmc = (b * MM + m) * CC + c;
    ((float4*)g_send)[bmc * D4 + tid] = s;
    if (tid == 0)
        g_A[bmc] = expf(-(s_red[0] + s_red[1]) * inv_tau);
}

// ---------------------------------------------------------------------------
// Phase 2: sequential scan across chunks per (b,m,d):
//   s_in[c] written, then s = A[c]*s + s_end[c].
// 16384 threads total; fully coalesced; L2-resident.
// ---------------------------------------------------------------------------
__global__ void __launch_bounds__(256) lc_phase2()
{
    const int idx = blockIdx.x * blockDim.x + threadIdx.x;  // (b*M+m)*D + d
    const int d  = idx % DD;
    const int bm = idx / DD;

    float s = 0.0f;
    #pragma unroll
    for (int c = 0; c < CC; c++) {
        const int base = (bm * CC + c) * DD + d;
        g_sin[base] = s;
        s = fmaf(g_A[bm * CC + c], s, g_send[base]);
    }
}

// ---------------------------------------------------------------------------
// Phase 3: re-scan each chunk from its true s_in and stream the output.
// grid = (C, M, B), block = 64 threads, float4 stores (STG.128).
// ---------------------------------------------------------------------------
__global__ void __launch_bounds__(64) lc_phase3(
    const float* __restrict__ x, const float* __restrict__ delta,
    const float* __restrict__ tau, float* __restrict__ out)
{
    const int c = blockIdx.x, m = blockIdx.y, b = blockIdx.z;
    const int tid = threadIdx.x;

    __shared__ float s_alpha[LL];

    const float inv_tau = 1.0f / tau[m];
    const int t0 = c * LL;
    const float* drow = delta + b * TT;

    #pragma unroll
    for (int i = tid; i < LL; i += 64) {
        const int t = t0 + i;
        float dt = (t == 0) ? 0.0f : fmaxf(drow[t] - drow[t - 1], 0.0f);
        s_alpha[i] = expf(-dt * inv_tau);
    }
    __syncthreads();

    const int bmc = (b * MM + m) * CC + c;
    float4 s = ((const float4*)g_sin)[bmc * D4 + tid];

    const float4* xp = (const float4*)x + (b * TT + t0) * D4 + tid;
    float4* op = (float4*)out + ((b * TT + t0) * MM + m) * D4 + tid;

    #pragma unroll 4
    for (int i = 0; i < LL; i++) {
        const float a  = s_alpha[i];
        const float om = 1.0f - a;
        const float4 xv = xp[i * D4];
        s.x = fmaf(a, s.x, om * xv.x);
        s.y = fmaf(a, s.y, om * xv.y);
        s.z = fmaf(a, s.z, om * xv.z);
        s.w = fmaf(a, s.w, om * xv.w);
        op[i * (MM * D4)] = s;
    }
}

// ---------------------------------------------------------------------------
extern "C" void kernel_launch(void* const* d_in, const int* in_sizes, int n_in,
                              void* d_out, int out_size)
{
    const float* x     = (const float*)d_in[0];
    const float* delta = (const float*)d_in[1];
    const float* tau   = (const float*)d_in[2];
    float* out = (float*)d_out;

    dim3 grid(CC, MM, BB);
    lc_phase1<<<grid, 64>>>(x, delta, tau);
    lc_phase2<<<64, 256>>>();
    lc_phase3<<<grid, 64>>>(x, delta, tau, out);
}